// round 5
// baseline (speedup 1.0000x reference)
#include <cuda_runtime.h>
#include <cuda_fp16.h>
#include <cstdint>

// GraphConv: out = relu( segment_sum(feature[src] -> dst) @ W^T + b )
// R5: fp16 feature cache + capacity-binned CSR + fused gather+tf32-MMA+epilogue.

constexpr int N_NODES = 50000;
constexpr int N_EDGES = 800000;
constexpr int D       = 128;
constexpr int CAP     = 128;        // per-node bin capacity (Poisson(16), max ~45)

// ---- static scratch ----
__device__ __half g_feat16[N_NODES * D];     // 12.8 MB fp16 feature cache
__device__ int    g_bins[N_NODES * CAP];     // 25.6 MB binned src ids
__device__ int    g_cursor[N_NODES];         // fill cursor == in-degree
__device__ int    g_ovf_cnt;
__device__ int2   g_ovf[N_EDGES];            // overflow edges (unconditionally correct)

// ---------------------------------------------------------------------------
// 1) prep: convert feature -> fp16, zero cursors + overflow counter
// ---------------------------------------------------------------------------
__global__ void __launch_bounds__(256) prep_kernel(const float4* __restrict__ feat)
{
    int i = blockIdx.x * blockDim.x + threadIdx.x;
    if (i < N_NODES * D / 8) {
        float4 a = feat[i * 2];
        float4 b = feat[i * 2 + 1];
        __half2 h0 = __floats2half2_rn(a.x, a.y);
        __half2 h1 = __floats2half2_rn(a.z, a.w);
        __half2 h2 = __floats2half2_rn(b.x, b.y);
        __half2 h3 = __floats2half2_rn(b.z, b.w);
        uint4 v;
        v.x = *reinterpret_cast<uint32_t*>(&h0);
        v.y = *reinterpret_cast<uint32_t*>(&h1);
        v.z = *reinterpret_cast<uint32_t*>(&h2);
        v.w = *reinterpret_cast<uint32_t*>(&h3);
        reinterpret_cast<uint4*>(g_feat16)[i] = v;
    }
    if (i < N_NODES) g_cursor[i] = 0;
    if (i == 0) g_ovf_cnt = 0;
}

// ---------------------------------------------------------------------------
// 2) bin fill: g_bins[dst*CAP + pos] = src
// ---------------------------------------------------------------------------
__global__ void __launch_bounds__(256) fill_kernel(const int* __restrict__ ei)
{
    int e = blockIdx.x * blockDim.x + threadIdx.x;
    if (e >= N_EDGES) return;
    int src = __ldg(&ei[e]);
    int dst = __ldg(&ei[N_EDGES + e]);
    int pos = atomicAdd(&g_cursor[dst], 1);
    if (pos < CAP) {
        g_bins[dst * CAP + pos] = src;
    } else {
        int o = atomicAdd(&g_ovf_cnt, 1);
        g_ovf[o] = make_int2(src, dst);
    }
}

// ---------------------------------------------------------------------------
// 3) fused: gather 64-node A-tile into smem (fp16), tf32 MMA vs W, bias+relu.
//    128 threads = 4 warps; warp w owns rows [w*16, w*16+16).
// ---------------------------------------------------------------------------
constexpr int TM     = 64;    // nodes per block
constexpr int APAD   = 132;   // As row stride in halfs (66 words: conflict-free)
constexpr int KPAD_B = 33;    // Bs row stride in words (2-way worst case)

__device__ __forceinline__ uint32_t f32_to_tf32(float f) {
    uint32_t r;
    asm volatile("cvt.rna.tf32.f32 %0, %1;" : "=r"(r) : "f"(f));
    return r;
}

__device__ __forceinline__ void mma_tf32(
    float& d0, float& d1, float& d2, float& d3,
    uint32_t a0, uint32_t a1, uint32_t a2, uint32_t a3,
    uint32_t b0, uint32_t b1)
{
    asm volatile(
        "mma.sync.aligned.m16n8k8.row.col.f32.tf32.tf32.f32 "
        "{%0,%1,%2,%3}, {%4,%5,%6,%7}, {%8,%9}, {%0,%1,%2,%3};"
        : "+f"(d0), "+f"(d1), "+f"(d2), "+f"(d3)
        : "r"(a0), "r"(a1), "r"(a2), "r"(a3), "r"(b0), "r"(b1));
}

__device__ __forceinline__ void acc_add(float4& a, uint2 u) {
    __half2 h0 = *reinterpret_cast<__half2*>(&u.x);
    __half2 h1 = *reinterpret_cast<__half2*>(&u.y);
    float2 f0 = __half22float2(h0);
    float2 f1 = __half22float2(h1);
    a.x += f0.x; a.y += f0.y; a.z += f1.x; a.w += f1.y;
}

__global__ void __launch_bounds__(128, 4) fused_kernel(
    const float* __restrict__ Wm, const float* __restrict__ bias,
    float* __restrict__ out)
{
    __shared__ __half   As[TM * APAD];       // gathered agg tile (fp16)
    __shared__ uint32_t Bs[128 * KPAD_B];    // W chunk (tf32)

    const int t    = threadIdx.x;
    const int lane = t & 31;
    const int w    = t >> 5;                 // warp 0..3
    const int m0   = blockIdx.x * TM;
    const int gp   = lane >> 2;
    const int tg   = lane & 3;

    const uint2* f = reinterpret_cast<const uint2*>(g_feat16);  // 32 uint2 per row

    // ---- gather phase: warp w fills rows w*16 .. w*16+15 of As ----
    for (int i = 0; i < 16; i++) {
        int r    = w * 16 + i;
        int node = m0 + r;
        float4 acc = make_float4(0.f, 0.f, 0.f, 0.f);
        if (node < N_NODES) {
            int degf = g_cursor[node];
            int deg  = min(degf, CAP);
            const int* bin = &g_bins[node * CAP];
            int e = 0;
            for (; e + 4 <= deg; e += 4) {
                int s0 = bin[e];
                int s1 = bin[e + 1];
                int s2 = bin[e + 2];
                int s3 = bin[e + 3];
                uint2 u0 = f[s0 * 32 + lane];
                uint2 u1 = f[s1 * 32 + lane];
                uint2 u2 = f[s2 * 32 + lane];
                uint2 u3 = f[s3 * 32 + lane];
                acc_add(acc, u0); acc_add(acc, u1);
                acc_add(acc, u2); acc_add(acc, u3);
            }
            for (; e < deg; e++) {
                uint2 u = f[bin[e] * 32 + lane];
                acc_add(acc, u);
            }
            if (degf > CAP) {           // overflow fixup (expected never)
                int cnt = g_ovf_cnt;
                for (int j = 0; j < cnt; j++) {
                    int2 sd = g_ovf[j];
                    if (sd.y == node) {
                        uint2 u = f[sd.x * 32 + lane];
                        acc_add(acc, u);
                    }
                }
            }
        }
        __half2 h0 = __floats2half2_rn(acc.x, acc.y);
        __half2 h1 = __floats2half2_rn(acc.z, acc.w);
        uint2 st;
        st.x = *reinterpret_cast<uint32_t*>(&h0);
        st.y = *reinterpret_cast<uint32_t*>(&h1);
        *reinterpret_cast<uint2*>(&As[r * APAD + lane * 4]) = st;
    }
    __syncthreads();

    // ---- GEMM phase: stream W in 32-k chunks, tf32 MMA ----
    float acc[16][4];
#pragma unroll
    for (int nt = 0; nt < 16; nt++)
#pragma unroll
        for (int j = 0; j < 4; j++) acc[nt][j] = 0.f;

    for (int k0 = 0; k0 < D; k0 += 32) {
        // stage Bs: thread t loads row n=t of W chunk (32 floats)
        {
            const float4* wrow = reinterpret_cast<const float4*>(Wm + t * D + k0);
#pragma unroll
            for (int q = 0; q < 8; q++) {
                float4 v = wrow[q];
                uint32_t* d = &Bs[t * KPAD_B + q * 4];
                d[0] = f32_to_tf32(v.x);
                d[1] = f32_to_tf32(v.y);
                d[2] = f32_to_tf32(v.z);
                d[3] = f32_to_tf32(v.w);
            }
        }
        __syncthreads();

#pragma unroll
        for (int kk = 0; kk < 4; kk++) {
            int kb = k0 + kk * 8;   // absolute k for As; relative for Bs
            int kr = kk * 8;
            int ar = w * 16 + gp;
            uint32_t a0 = f32_to_tf32(__half2float(As[(ar    ) * APAD + kb + tg    ]));
            uint32_t a1 = f32_to_tf32(__half2float(As[(ar + 8) * APAD + kb + tg    ]));
            uint32_t a2 = f32_to_tf32(__half2float(As[(ar    ) * APAD + kb + tg + 4]));
            uint32_t a3 = f32_to_tf32(__half2float(As[(ar + 8) * APAD + kb + tg + 4]));
#pragma unroll
            for (int nt = 0; nt < 16; nt++) {
                int n = nt * 8 + gp;
                uint32_t b0 = Bs[n * KPAD_B + kr + tg    ];
                uint32_t b1 = Bs[n * KPAD_B + kr + tg + 4];
                mma_tf32(acc[nt][0], acc[nt][1], acc[nt][2], acc[nt][3],
                         a0, a1, a2, a3, b0, b1);
            }
        }
        __syncthreads();
    }

    // ---- epilogue: + bias, relu, store ----
    int r0 = m0 + w * 16 + gp;
#pragma unroll
    for (int nt = 0; nt < 16; nt++) {
        int c  = nt * 8 + tg * 2;
        float b0 = __ldg(&bias[c]);
        float b1 = __ldg(&bias[c + 1]);
        if (r0 < N_NODES) {
            float2 v;
            v.x = fmaxf(acc[nt][0] + b0, 0.f);
            v.y = fmaxf(acc[nt][1] + b1, 0.f);
            *reinterpret_cast<float2*>(out + r0 * D + c) = v;
        }
        if (r0 + 8 < N_NODES) {
            float2 v;
            v.x = fmaxf(acc[nt][2] + b0, 0.f);
            v.y = fmaxf(acc[nt][3] + b1, 0.f);
            *reinterpret_cast<float2*>(out + (r0 + 8) * D + c) = v;
        }
    }
}

// ---------------------------------------------------------------------------
extern "C" void kernel_launch(void* const* d_in, const int* in_sizes, int n_in,
                              void* d_out, int out_size)
{
    const float* feature = (const float*)d_in[0];   // [50000,128]
    const float* Wm      = (const float*)d_in[1];   // [128,128]
    const float* bias    = (const float*)d_in[2];   // [128]
    const int*   ei      = (const int*)  d_in[3];   // [2,800000]
    float*       out     = (float*)d_out;           // [50000,128]

    (void)in_sizes; (void)n_in; (void)out_size;

    prep_kernel<<<(N_NODES * D / 8 + 255) / 256, 256>>>(
        reinterpret_cast<const float4*>(feature));
    fill_kernel<<<(N_EDGES + 255) / 256, 256>>>(ei);
    {
        int blocks = (N_NODES + TM - 1) / TM;   // 782
        fused_kernel<<<blocks, 128>>>(Wm, bias, out);
    }
}

// round 7
// speedup vs baseline: 1.7564x; 1.7564x over previous
#include <cuda_runtime.h>
#include <cuda_fp16.h>
#include <cstdint>

// GraphConv: out = relu( segment_sum(feature[src] -> dst) @ W^T + b )
// R7: R6 with the GEMM A-tile staging fix (full 32-k chunk coverage).
//   1) prep: feature->fp16, zero cursors
//   2) fill: capacity-binned CSR
//   3) gather: warp-per-node, fp16 loads, fp32 accum, fp16 agg store
//   4) GEMM: tf32 MMA reading fp16 agg

constexpr int N_NODES = 50000;
constexpr int N_EDGES = 800000;
constexpr int D       = 128;
constexpr int CAP     = 128;

// ---- static scratch ----
__device__ __half g_feat16[N_NODES * D];     // 12.8 MB fp16 feature cache
__device__ __half g_agg16[N_NODES * D];      // 12.8 MB fp16 aggregated features
__device__ int    g_bins[N_NODES * CAP];     // 25.6 MB binned src ids
__device__ int    g_cursor[N_NODES];         // fill cursor == in-degree
__device__ int    g_ovf_cnt;
__device__ int2   g_ovf[N_EDGES];            // overflow edges (correctness net)

// ---------------------------------------------------------------------------
// 1) prep: convert feature -> fp16, zero cursors + overflow counter
// ---------------------------------------------------------------------------
__global__ void __launch_bounds__(256) prep_kernel(const float4* __restrict__ feat)
{
    int i = blockIdx.x * blockDim.x + threadIdx.x;
    if (i < N_NODES * D / 8) {
        float4 a = feat[i * 2];
        float4 b = feat[i * 2 + 1];
        __half2 h0 = __floats2half2_rn(a.x, a.y);
        __half2 h1 = __floats2half2_rn(a.z, a.w);
        __half2 h2 = __floats2half2_rn(b.x, b.y);
        __half2 h3 = __floats2half2_rn(b.z, b.w);
        uint4 v;
        v.x = *reinterpret_cast<uint32_t*>(&h0);
        v.y = *reinterpret_cast<uint32_t*>(&h1);
        v.z = *reinterpret_cast<uint32_t*>(&h2);
        v.w = *reinterpret_cast<uint32_t*>(&h3);
        reinterpret_cast<uint4*>(g_feat16)[i] = v;
    }
    if (i < N_NODES) g_cursor[i] = 0;
    if (i == 0) g_ovf_cnt = 0;
}

// ---------------------------------------------------------------------------
// 2) bin fill
// ---------------------------------------------------------------------------
__global__ void __launch_bounds__(256) fill_kernel(const int* __restrict__ ei)
{
    int e = blockIdx.x * blockDim.x + threadIdx.x;
    if (e >= N_EDGES) return;
    int src = __ldg(&ei[e]);
    int dst = __ldg(&ei[N_EDGES + e]);
    int pos = atomicAdd(&g_cursor[dst], 1);
    if (pos < CAP) {
        g_bins[dst * CAP + pos] = src;
    } else {
        int o = atomicAdd(&g_ovf_cnt, 1);
        g_ovf[o] = make_int2(src, dst);
    }
}

// ---------------------------------------------------------------------------
// 3) gather: warp-per-node, lane owns 4 halfs (uint2), fp32 accumulation.
// ---------------------------------------------------------------------------
__device__ __forceinline__ void acc_add(float4& a, uint2 u) {
    __half2 h0 = *reinterpret_cast<__half2*>(&u.x);
    __half2 h1 = *reinterpret_cast<__half2*>(&u.y);
    float2 f0 = __half22float2(h0);
    float2 f1 = __half22float2(h1);
    a.x += f0.x; a.y += f0.y; a.z += f1.x; a.w += f1.y;
}

__global__ void __launch_bounds__(256) gather_kernel()
{
    int warp = (blockIdx.x * blockDim.x + threadIdx.x) >> 5;
    int lane = threadIdx.x & 31;
    if (warp >= N_NODES) return;

    const uint2* f = reinterpret_cast<const uint2*>(g_feat16);  // 32 uint2/row

    int degf = g_cursor[warp];
    int deg  = min(degf, CAP);
    const int* bin = &g_bins[warp * CAP];

    float4 acc = make_float4(0.f, 0.f, 0.f, 0.f);

    int e = 0;
    for (; e + 4 <= deg; e += 4) {
        int s0 = bin[e];
        int s1 = bin[e + 1];
        int s2 = bin[e + 2];
        int s3 = bin[e + 3];
        uint2 u0 = f[s0 * 32 + lane];
        uint2 u1 = f[s1 * 32 + lane];
        uint2 u2 = f[s2 * 32 + lane];
        uint2 u3 = f[s3 * 32 + lane];
        acc_add(acc, u0); acc_add(acc, u1);
        acc_add(acc, u2); acc_add(acc, u3);
    }
    for (; e < deg; e++) {
        uint2 u = f[bin[e] * 32 + lane];
        acc_add(acc, u);
    }

    if (degf > CAP) {                 // inline overflow fixup (expected never)
        int cnt = g_ovf_cnt;
        for (int j = 0; j < cnt; j++) {
            int2 sd = g_ovf[j];
            if (sd.y == warp) {
                uint2 u = f[sd.x * 32 + lane];
                acc_add(acc, u);
            }
        }
    }

    __half2 h0 = __floats2half2_rn(acc.x, acc.y);
    __half2 h1 = __floats2half2_rn(acc.z, acc.w);
    uint2 st;
    st.x = *reinterpret_cast<uint32_t*>(&h0);
    st.y = *reinterpret_cast<uint32_t*>(&h1);
    reinterpret_cast<uint2*>(g_agg16)[warp * 32 + lane] = st;
}

// ---------------------------------------------------------------------------
// 4) GEMM via tf32 mma.sync:  out = relu( agg16 @ W^T + b )
//    Block: 128 rows x 128 cols, 256 threads (8 warps), K chunks of 32.
// ---------------------------------------------------------------------------
constexpr int GM = 128;
constexpr int CK = 32;
constexpr int KPAD = 36;

__device__ __forceinline__ uint32_t f32_to_tf32(float f) {
    uint32_t r;
    asm volatile("cvt.rna.tf32.f32 %0, %1;" : "=r"(r) : "f"(f));
    return r;
}

__device__ __forceinline__ void mma_tf32(
    float& d0, float& d1, float& d2, float& d3,
    uint32_t a0, uint32_t a1, uint32_t a2, uint32_t a3,
    uint32_t b0, uint32_t b1)
{
    asm volatile(
        "mma.sync.aligned.m16n8k8.row.col.f32.tf32.tf32.f32 "
        "{%0,%1,%2,%3}, {%4,%5,%6,%7}, {%8,%9}, {%0,%1,%2,%3};"
        : "+f"(d0), "+f"(d1), "+f"(d2), "+f"(d3)
        : "r"(a0), "r"(a1), "r"(a2), "r"(a3), "r"(b0), "r"(b1));
}

__global__ void __launch_bounds__(256, 1) gemm_tf32_bias_relu_kernel(
    const float* __restrict__ Wm, const float* __restrict__ bias,
    float* __restrict__ out)
{
    __shared__ uint32_t As[GM * KPAD];
    __shared__ uint32_t Bs[128 * KPAD];

    const int t    = threadIdx.x;
    const int lane = t & 31;
    const int w    = t >> 5;
    const int m0   = blockIdx.x * GM;

    const int gp  = lane >> 2;
    const int tg  = lane & 3;

    float acc[16][4];
#pragma unroll
    for (int nt = 0; nt < 16; nt++)
#pragma unroll
        for (int j = 0; j < 4; j++) acc[nt][j] = 0.f;

    for (int k0 = 0; k0 < D; k0 += CK) {
        // ---- stage A chunk from fp16 agg: 128 rows x 32 k ----
        // FIX (R6 bug): 8 uint2 per row (32 halfs), not 4.
        // 128 rows * 8 uint2 = 1024 uint2 / 256 threads = 4 each.
#pragma unroll
        for (int i = 0; i < 4; i++) {
            int lin = t + i * 256;          // 0..1023
            int row = lin >> 3;             // 0..127
            int q   = lin & 7;              // uint2 index within 32-half chunk
            int m   = m0 + row;
            uint2 u = make_uint2(0u, 0u);
            if (m < N_NODES)
                u = *reinterpret_cast<const uint2*>(g_agg16 + m * D + k0 + q * 4);
            __half2 h0 = *reinterpret_cast<__half2*>(&u.x);
            __half2 h1 = *reinterpret_cast<__half2*>(&u.y);
            float2 f0 = __half22float2(h0);
            float2 f1 = __half22float2(h1);
            uint32_t* dstp = &As[row * KPAD + q * 4];
            dstp[0] = f32_to_tf32(f0.x);
            dstp[1] = f32_to_tf32(f0.y);
            dstp[2] = f32_to_tf32(f1.x);
            dstp[3] = f32_to_tf32(f1.y);
        }
        // ---- stage W chunk: 128 n x 32 k ----
#pragma unroll
        for (int i = 0; i < 4; i++) {
            int lin = t + i * 256;
            int n   = lin >> 3;
            int q   = lin & 7;
            float4 v = *reinterpret_cast<const float4*>(Wm + n * D + k0 + q * 4);
            uint32_t* dstp = &Bs[n * KPAD + q * 4];
            dstp[0] = f32_to_tf32(v.x);
            dstp[1] = f32_to_tf32(v.y);
            dstp[2] = f32_to_tf32(v.z);
            dstp[3] = f32_to_tf32(v.w);
        }
        __syncthreads();

#pragma unroll
        for (int kk = 0; kk < 4; kk++) {
            int kb = kk * 8;
            int ar = w * 16 + gp;
            uint32_t a0 = As[(ar    ) * KPAD + kb + tg    ];
            uint32_t a1 = As[(ar + 8) * KPAD + kb + tg    ];
            uint32_t a2 = As[(ar    ) * KPAD + kb + tg + 4];
            uint32_t a3 = As[(ar + 8) * KPAD + kb + tg + 4];
#pragma unroll
            for (int nt = 0; nt < 16; nt++) {
                int n = nt * 8 + gp;
                uint32_t b0 = Bs[n * KPAD + kb + tg    ];
                uint32_t b1 = Bs[n * KPAD + kb + tg + 4];
                mma_tf32(acc[nt][0], acc[nt][1], acc[nt][2], acc[nt][3],
                         a0, a1, a2, a3, b0, b1);
            }
        }
        __syncthreads();
    }

    int r0 = m0 + w * 16 + gp;
#pragma unroll
    for (int nt = 0; nt < 16; nt++) {
        int c = nt * 8 + tg * 2;
        float b0 = __ldg(&bias[c]);
        float b1 = __ldg(&bias[c + 1]);
        if (r0 < N_NODES) {
            float2 v;
            v.x = fmaxf(acc[nt][0] + b0, 0.f);
            v.y = fmaxf(acc[nt][1] + b1, 0.f);
            *reinterpret_cast<float2*>(out + r0 * D + c) = v;
        }
        if (r0 + 8 < N_NODES) {
            float2 v;
            v.x = fmaxf(acc[nt][2] + b0, 0.f);
            v.y = fmaxf(acc[nt][3] + b1, 0.f);
            *reinterpret_cast<float2*>(out + (r0 + 8) * D + c) = v;
        }
    }
}

// ---------------------------------------------------------------------------
extern "C" void kernel_launch(void* const* d_in, const int* in_sizes, int n_in,
                              void* d_out, int out_size)
{
    const float* feature = (const float*)d_in[0];   // [50000,128]
    const float* Wm      = (const float*)d_in[1];   // [128,128]
    const float* bias    = (const float*)d_in[2];   // [128]
    const int*   ei      = (const int*)  d_in[3];   // [2,800000]
    float*       out     = (float*)d_out;           // [50000,128]

    (void)in_sizes; (void)n_in; (void)out_size;

    prep_kernel<<<(N_NODES * D / 8 + 255) / 256, 256>>>(
        reinterpret_cast<const float4*>(feature));
    fill_kernel<<<(N_EDGES + 255) / 256, 256>>>(ei);
    {
        int total_threads = N_NODES * 32;
        gather_kernel<<<(total_threads + 255) / 256, 256>>>();
    }
    {
        int blocks = (N_NODES + GM - 1) / GM;
        gemm_tf32_bias_relu_kernel<<<blocks, 256>>>(Wm, bias, out);
    }
}

// round 9
// speedup vs baseline: 1.9155x; 1.0906x over previous
#include <cuda_runtime.h>
#include <cuda_fp16.h>
#include <cstdint>

// GraphConv: out = relu( segment_sum(feature[src] -> dst) @ W^T + b )
// R9: R7 + MLP-4 fill + fp16 HMMA GEMM (full-K smem tiles) + unroll-8 gather.

constexpr int N_NODES = 50000;
constexpr int N_EDGES = 800000;
constexpr int D       = 128;
constexpr int CAP     = 128;

// ---- static scratch ----
__device__ __half g_feat16[N_NODES * D];     // 12.8 MB fp16 feature cache
__device__ __half g_agg16[N_NODES * D];      // 12.8 MB fp16 aggregated features
__device__ int    g_bins[N_NODES * CAP];     // 25.6 MB binned src ids
__device__ int    g_cursor[N_NODES];         // fill cursor == in-degree
__device__ int    g_ovf_cnt;
__device__ int2   g_ovf[N_EDGES];            // overflow edges (correctness net)

// ---------------------------------------------------------------------------
// 1) prep: convert feature -> fp16, zero cursors + overflow counter
// ---------------------------------------------------------------------------
__global__ void __launch_bounds__(256) prep_kernel(const float4* __restrict__ feat)
{
    int i = blockIdx.x * blockDim.x + threadIdx.x;
    if (i < N_NODES * D / 8) {
        float4 a = feat[i * 2];
        float4 b = feat[i * 2 + 1];
        __half2 h0 = __floats2half2_rn(a.x, a.y);
        __half2 h1 = __floats2half2_rn(a.z, a.w);
        __half2 h2 = __floats2half2_rn(b.x, b.y);
        __half2 h3 = __floats2half2_rn(b.z, b.w);
        uint4 v;
        v.x = *reinterpret_cast<uint32_t*>(&h0);
        v.y = *reinterpret_cast<uint32_t*>(&h1);
        v.z = *reinterpret_cast<uint32_t*>(&h2);
        v.w = *reinterpret_cast<uint32_t*>(&h3);
        reinterpret_cast<uint4*>(g_feat16)[i] = v;
    }
    if (i < N_NODES) g_cursor[i] = 0;
    if (i == 0) g_ovf_cnt = 0;
}

// ---------------------------------------------------------------------------
// 2) bin fill: 4 edges per thread, independent atomic chains (MLP=4)
// ---------------------------------------------------------------------------
__device__ __forceinline__ void fill_one(int src, int dst, int pos) {
    if (pos < CAP) {
        g_bins[dst * CAP + pos] = src;
    } else {
        int o = atomicAdd(&g_ovf_cnt, 1);
        g_ovf[o] = make_int2(src, dst);
    }
}

__global__ void __launch_bounds__(256) fill_kernel(const int* __restrict__ ei)
{
    int i = blockIdx.x * blockDim.x + threadIdx.x;   // 0 .. N_EDGES/4-1
    if (i >= N_EDGES / 4) return;
    int4 s = reinterpret_cast<const int4*>(ei)[i];
    int4 d = reinterpret_cast<const int4*>(ei + N_EDGES)[i];
    int p0 = atomicAdd(&g_cursor[d.x], 1);
    int p1 = atomicAdd(&g_cursor[d.y], 1);
    int p2 = atomicAdd(&g_cursor[d.z], 1);
    int p3 = atomicAdd(&g_cursor[d.w], 1);
    fill_one(s.x, d.x, p0);
    fill_one(s.y, d.y, p1);
    fill_one(s.z, d.z, p2);
    fill_one(s.w, d.w, p3);
}

// ---------------------------------------------------------------------------
// 3) gather: warp-per-node, lane owns 4 halfs (uint2), fp32 accum, unroll 8.
// ---------------------------------------------------------------------------
__device__ __forceinline__ void acc_add(float4& a, uint2 u) {
    __half2 h0 = *reinterpret_cast<__half2*>(&u.x);
    __half2 h1 = *reinterpret_cast<__half2*>(&u.y);
    float2 f0 = __half22float2(h0);
    float2 f1 = __half22float2(h1);
    a.x += f0.x; a.y += f0.y; a.z += f1.x; a.w += f1.y;
}

__global__ void __launch_bounds__(256) gather_kernel()
{
    int warp = (blockIdx.x * blockDim.x + threadIdx.x) >> 5;
    int lane = threadIdx.x & 31;
    if (warp >= N_NODES) return;

    const uint2* f = reinterpret_cast<const uint2*>(g_feat16);  // 32 uint2/row

    int degf = g_cursor[warp];
    int deg  = min(degf, CAP);
    const int* bin = &g_bins[warp * CAP];

    float4 acc = make_float4(0.f, 0.f, 0.f, 0.f);

    int e = 0;
    for (; e + 8 <= deg; e += 8) {
        int s0 = bin[e];     int s1 = bin[e + 1];
        int s2 = bin[e + 2]; int s3 = bin[e + 3];
        int s4 = bin[e + 4]; int s5 = bin[e + 5];
        int s6 = bin[e + 6]; int s7 = bin[e + 7];
        uint2 u0 = f[s0 * 32 + lane];
        uint2 u1 = f[s1 * 32 + lane];
        uint2 u2 = f[s2 * 32 + lane];
        uint2 u3 = f[s3 * 32 + lane];
        uint2 u4 = f[s4 * 32 + lane];
        uint2 u5 = f[s5 * 32 + lane];
        uint2 u6 = f[s6 * 32 + lane];
        uint2 u7 = f[s7 * 32 + lane];
        acc_add(acc, u0); acc_add(acc, u1);
        acc_add(acc, u2); acc_add(acc, u3);
        acc_add(acc, u4); acc_add(acc, u5);
        acc_add(acc, u6); acc_add(acc, u7);
    }
    for (; e + 4 <= deg; e += 4) {
        int s0 = bin[e];     int s1 = bin[e + 1];
        int s2 = bin[e + 2]; int s3 = bin[e + 3];
        uint2 u0 = f[s0 * 32 + lane];
        uint2 u1 = f[s1 * 32 + lane];
        uint2 u2 = f[s2 * 32 + lane];
        uint2 u3 = f[s3 * 32 + lane];
        acc_add(acc, u0); acc_add(acc, u1);
        acc_add(acc, u2); acc_add(acc, u3);
    }
    for (; e < deg; e++) {
        uint2 u = f[bin[e] * 32 + lane];
        acc_add(acc, u);
    }

    if (degf > CAP) {                 // inline overflow fixup (expected never)
        int cnt = g_ovf_cnt;
        for (int j = 0; j < cnt; j++) {
            int2 sd = g_ovf[j];
            if (sd.y == warp) {
                uint2 u = f[sd.x * 32 + lane];
                acc_add(acc, u);
            }
        }
    }

    __half2 h0 = __floats2half2_rn(acc.x, acc.y);
    __half2 h1 = __floats2half2_rn(acc.z, acc.w);
    uint2 st;
    st.x = *reinterpret_cast<uint32_t*>(&h0);
    st.y = *reinterpret_cast<uint32_t*>(&h1);
    reinterpret_cast<uint2*>(g_agg16)[warp * 32 + lane] = st;
}

// ---------------------------------------------------------------------------
// 4) GEMM via fp16 mma m16n8k16 (fp32 accum): out = relu( agg16 @ W^T + b )
//    Block: 128 rows x 128 cols, 256 threads (8 warps).
//    Full-K smem tiles: As[128][136] half, Bs[128][136] half (69.6 KB dynamic).
//    Stride 136 halfs => word addr 68*row + tg => banks 4*row+tg (conflict-free).
// ---------------------------------------------------------------------------
constexpr int GM    = 128;
constexpr int ASTR  = 136;                       // half stride per row
constexpr int SMEM_BYTES = 2 * GM * ASTR * 2;    // 69632

__device__ __forceinline__ void mma_f16(
    float& d0, float& d1, float& d2, float& d3,
    uint32_t a0, uint32_t a1, uint32_t a2, uint32_t a3,
    uint32_t b0, uint32_t b1)
{
    asm volatile(
        "mma.sync.aligned.m16n8k16.row.col.f32.f16.f16.f32 "
        "{%0,%1,%2,%3}, {%4,%5,%6,%7}, {%8,%9}, {%0,%1,%2,%3};"
        : "+f"(d0), "+f"(d1), "+f"(d2), "+f"(d3)
        : "r"(a0), "r"(a1), "r"(a2), "r"(a3), "r"(b0), "r"(b1));
}

__global__ void __launch_bounds__(256) gemm_f16_bias_relu_kernel(
    const float* __restrict__ Wm, const float* __restrict__ bias,
    float* __restrict__ out)
{
    extern __shared__ __half sm[];
    __half* As = sm;               // [128][136]
    __half* Bs = sm + GM * ASTR;   // [128][136]

    const int t    = threadIdx.x;
    const int lane = t & 31;
    const int w    = t >> 5;
    const int m0   = blockIdx.x * GM;
    const int gp   = lane >> 2;
    const int tg   = lane & 3;

    // ---- stage A (fp16 copy): 128 rows x 16 uint4 = 2048 / 256 thr = 8 each ----
#pragma unroll
    for (int i = 0; i < 8; i++) {
        int lin = t + i * 256;          // 0..2047
        int row = lin >> 4;             // 0..127
        int q   = lin & 15;             // uint4 (8 halfs) within row
        int m   = m0 + row;
        uint4 v = make_uint4(0u, 0u, 0u, 0u);
        if (m < N_NODES)
            v = reinterpret_cast<const uint4*>(g_agg16 + m * D)[q];
        *reinterpret_cast<uint4*>(&As[row * ASTR + q * 8]) = v;
    }
    // ---- stage W (fp32 -> fp16): thread handles half a row (64 floats) ----
    {
        int n    = t >> 1;              // 0..127
        int half = t & 1;               // which 64-float half
        const float4* wr = reinterpret_cast<const float4*>(Wm + n * D + half * 64);
#pragma unroll
        for (int q = 0; q < 16; q++) {
            float4 v = wr[q];
            __half2 h0 = __floats2half2_rn(v.x, v.y);
            __half2 h1 = __floats2half2_rn(v.z, v.w);
            uint2 u;
            u.x = *reinterpret_cast<uint32_t*>(&h0);
            u.y = *reinterpret_cast<uint32_t*>(&h1);
            *reinterpret_cast<uint2*>(&Bs[n * ASTR + half * 64 + q * 4]) = u;
        }
    }
    __syncthreads();

    float acc[16][4];
#pragma unroll
    for (int nt = 0; nt < 16; nt++)
#pragma unroll
        for (int j = 0; j < 4; j++) acc[nt][j] = 0.f;

    const int ar = w * 16 + gp;
#pragma unroll
    for (int ks = 0; ks < 8; ks++) {
        int kb = ks * 16;
        uint32_t a0 = *reinterpret_cast<uint32_t*>(&As[(ar    ) * ASTR + kb + 2 * tg    ]);
        uint32_t a1 = *reinterpret_cast<uint32_t*>(&As[(ar + 8) * ASTR + kb + 2 * tg    ]);
        uint32_t a2 = *reinterpret_cast<uint32_t*>(&As[(ar    ) * ASTR + kb + 2 * tg + 8]);
        uint32_t a3 = *reinterpret_cast<uint32_t*>(&As[(ar + 8) * ASTR + kb + 2 * tg + 8]);
#pragma unroll
        for (int nt = 0; nt < 16; nt++) {
            int n = nt * 8 + gp;
            uint32_t b0 = *reinterpret_cast<uint32_t*>(&Bs[n * ASTR + kb + 2 * tg    ]);
            uint32_t b1 = *reinterpret_cast<uint32_t*>(&Bs[n * ASTR + kb + 2 * tg + 8]);
            mma_f16(acc[nt][0], acc[nt][1], acc[nt][2], acc[nt][3],
                    a0, a1, a2, a3, b0, b1);
        }
    }

    // ---- epilogue: + bias, relu, store ----
    int r0 = m0 + ar;
#pragma unroll
    for (int nt = 0; nt < 16; nt++) {
        int c = nt * 8 + tg * 2;
        float b0 = __ldg(&bias[c]);
        float b1 = __ldg(&bias[c + 1]);
        if (r0 < N_NODES) {
            float2 v;
            v.x = fmaxf(acc[nt][0] + b0, 0.f);
            v.y = fmaxf(acc[nt][1] + b1, 0.f);
            *reinterpret_cast<float2*>(out + r0 * D + c) = v;
        }
        if (r0 + 8 < N_NODES) {
            float2 v;
            v.x = fmaxf(acc[nt][2] + b0, 0.f);
            v.y = fmaxf(acc[nt][3] + b1, 0.f);
            *reinterpret_cast<float2*>(out + (r0 + 8) * D + c) = v;
        }
    }
}

// ---------------------------------------------------------------------------
extern "C" void kernel_launch(void* const* d_in, const int* in_sizes, int n_in,
                              void* d_out, int out_size)
{
    const float* feature = (const float*)d_in[0];   // [50000,128]
    const float* Wm      = (const float*)d_in[1];   // [128,128]
    const float* bias    = (const float*)d_in[2];   // [128]
    const int*   ei      = (const int*)  d_in[3];   // [2,800000]
    float*       out     = (float*)d_out;           // [50000,128]

    (void)in_sizes; (void)n_in; (void)out_size;

    cudaFuncSetAttribute(gemm_f16_bias_relu_kernel,
                         cudaFuncAttributeMaxDynamicSharedMemorySize, SMEM_BYTES);

    prep_kernel<<<(N_NODES * D / 8 + 255) / 256, 256>>>(
        reinterpret_cast<const float4*>(feature));
    fill_kernel<<<(N_EDGES / 4 + 255) / 256, 256>>>(ei);
    {
        int total_threads = N_NODES * 32;
        gather_kernel<<<(total_threads + 255) / 256, 256>>>();
    }
    {
        int blocks = (N_NODES + GM - 1) / GM;   // 391
        gemm_f16_bias_relu_kernel<<<blocks, 256, SMEM_BYTES>>>(Wm, bias, out);
    }
}